// round 3
// baseline (speedup 1.0000x reference)
#include <cuda_runtime.h>
#include <math.h>

// Problem constants
#define NB   64
#define SEQL 512
#define DIN  256
#define NF   256
#define KSZ  3
#define NJ   (KSZ * NF)   // 768

// Scratch for per-batch dynamic weights, transposed to [b][k][d][f]
// 64*3*256*256 floats = 50.3 MB (static __device__, allowed by harness rules)
__device__ float g_Wt[NB * KSZ * DIN * NF];

// GEMM tiling
constexpr int BM = 128;
constexpr int BN = 64;
constexpr int BK = 16;
constexpr int TM = 8;
constexpr int TN = 4;
// 256 threads: 16 (ty, M dir) x 16 (tx, N dir)

// ---------------------------------------------------------------------------
// Kernel 1: W_b = U @ (diag(sigmoid(z_b)) V) + B_w, written as Wt[b][k][d][f]
//   M = DIN (d) = 256, N = NJ (j=k*NF+f) = 768, K = DIN (e) = 256
// ---------------------------------------------------------------------------
__global__ __launch_bounds__(256, 2)
void dyn_weight_kernel(const float* __restrict__ z,   // (NB, DIN)
                       const float* __restrict__ U,   // (DIN, DIN)
                       const float* __restrict__ V,   // (DIN, NJ)
                       const float* __restrict__ Bw)  // (DIN, NJ)
{
    const int b   = blockIdx.z;
    const int m0  = blockIdx.y * BM;   // d offset
    const int n0  = blockIdx.x * BN;   // j offset
    const int tid = (int)threadIdx.x;

    __shared__ float As[BK][BM];
    __shared__ float Bs[BK][BN];

    const int ty = tid >> 4;           // 0..15
    const int tx = tid & 15;           // 0..15

    float acc[TM][TN];
    #pragma unroll
    for (int i = 0; i < TM; ++i)
        #pragma unroll
        for (int j = 0; j < TN; ++j) acc[i][j] = 0.f;

    const int la_i = tid >> 2;         // 0..63  (M index, two halves)
    const int la_k = (tid & 3) * 4;    // 0,4,8,12 (K index, float4)
    const int lb_k = tid >> 4;         // 0..15  (K index)
    const int lb_j = (tid & 15) * 4;   // 0..60  (N index, float4)

    for (int e0 = 0; e0 < DIN; e0 += BK) {
        // A tile: U[m0+i][e0+kk], stored transposed As[kk][i]
        #pragma unroll
        for (int h = 0; h < 2; ++h) {
            const int i = la_i + h * 64;
            const float4 v = *reinterpret_cast<const float4*>(
                &U[(size_t)(m0 + i) * DIN + e0 + la_k]);
            As[la_k + 0][i] = v.x;
            As[la_k + 1][i] = v.y;
            As[la_k + 2][i] = v.z;
            As[la_k + 3][i] = v.w;
        }
        // B tile: sigmoid(z[b][e]) * V[e][n0+j]
        {
            const int e = e0 + lb_k;
            const float zv = z[(size_t)b * DIN + e];
            const float s  = 1.f / (1.f + expf(-zv));
            const float4 v = *reinterpret_cast<const float4*>(
                &V[(size_t)e * NJ + n0 + lb_j]);
            *reinterpret_cast<float4*>(&Bs[lb_k][lb_j]) =
                make_float4(s * v.x, s * v.y, s * v.z, s * v.w);
        }
        __syncthreads();

        #pragma unroll
        for (int kk = 0; kk < BK; ++kk) {
            float a[TM], bb[TN];
            #pragma unroll
            for (int i = 0; i < TM; ++i) a[i] = As[kk][ty * TM + i];
            #pragma unroll
            for (int j = 0; j < TN; ++j) bb[j] = Bs[kk][tx * TN + j];
            #pragma unroll
            for (int i = 0; i < TM; ++i)
                #pragma unroll
                for (int j = 0; j < TN; ++j)
                    acc[i][j] = fmaf(a[i], bb[j], acc[i][j]);
        }
        __syncthreads();
    }

    // Epilogue: add B_w, scatter to Wt[b][k][d][f]
    const int j  = n0 + tx * TN;       // BN=64 divides NF=256 -> k constant per thread
    const int k  = j / NF;
    const int f  = j % NF;
    #pragma unroll
    for (int i = 0; i < TM; ++i) {
        const int d = m0 + ty * TM + i;
        const float4 bw = *reinterpret_cast<const float4*>(&Bw[(size_t)d * NJ + j]);
        const float4 o = make_float4(acc[i][0] + bw.x, acc[i][1] + bw.y,
                                     acc[i][2] + bw.z, acc[i][3] + bw.w);
        *reinterpret_cast<float4*>(
            &g_Wt[(((size_t)b * KSZ + k) * DIN + d) * NF + f]) = o;
    }
}

// ---------------------------------------------------------------------------
// Kernel 2: out[b,l,f] = relu( sum_k sum_d x[b,l+k-1,d] * Wt[b,k,d,f] + bias[f] )
//   Per batch: 3 shifted GEMMs (M=SEQ=512, N=NF=256, K=DIN=256)
// ---------------------------------------------------------------------------
__global__ __launch_bounds__(256, 2)
void conv_kernel(const float* __restrict__ x,     // (NB, SEQL, DIN)
                 const float* __restrict__ bias,  // (NF)
                 float* __restrict__ out)         // (NB, SEQL, NF)
{
    const int b   = blockIdx.z;
    const int l0  = blockIdx.y * BM;   // seq offset
    const int f0  = blockIdx.x * BN;   // filter offset
    const int tid = (int)threadIdx.x;

    __shared__ float As[BK][BM];
    __shared__ float Bs[BK][BN];

    const int ty = tid >> 4;
    const int tx = tid & 15;

    float acc[TM][TN];
    #pragma unroll
    for (int i = 0; i < TM; ++i)
        #pragma unroll
        for (int j = 0; j < TN; ++j) acc[i][j] = 0.f;

    const int la_i = tid >> 2;
    const int la_k = (tid & 3) * 4;
    const int lb_k = tid >> 4;
    const int lb_j = (tid & 15) * 4;

    for (int k = 0; k < KSZ; ++k) {
        for (int e0 = 0; e0 < DIN; e0 += BK) {
            // A tile: x[b, l0+i+k-1, e0+kk], zero-padded at sequence edges
            #pragma unroll
            for (int h = 0; h < 2; ++h) {
                const int i   = la_i + h * 64;
                const int row = l0 + i + k - 1;
                float4 v = make_float4(0.f, 0.f, 0.f, 0.f);
                if ((unsigned)row < (unsigned)SEQL)
                    v = *reinterpret_cast<const float4*>(
                        &x[((size_t)b * SEQL + row) * DIN + e0 + la_k]);
                As[la_k + 0][i] = v.x;
                As[la_k + 1][i] = v.y;
                As[la_k + 2][i] = v.z;
                As[la_k + 3][i] = v.w;
            }
            // B tile: Wt[b,k, e0+kk, f0+j]
            {
                const int d = e0 + lb_k;
                const float4 v = *reinterpret_cast<const float4*>(
                    &g_Wt[(((size_t)b * KSZ + k) * DIN + d) * NF + f0 + lb_j]);
                *reinterpret_cast<float4*>(&Bs[lb_k][lb_j]) = v;
            }
            __syncthreads();

            #pragma unroll
            for (int kk = 0; kk < BK; ++kk) {
                float a[TM], bb[TN];
                #pragma unroll
                for (int i = 0; i < TM; ++i) a[i] = As[kk][ty * TM + i];
                #pragma unroll
                for (int j = 0; j < TN; ++j) bb[j] = Bs[kk][tx * TN + j];
                #pragma unroll
                for (int i = 0; i < TM; ++i)
                    #pragma unroll
                    for (int j = 0; j < TN; ++j)
                        acc[i][j] = fmaf(a[i], bb[j], acc[i][j]);
            }
            __syncthreads();
        }
    }

    // Epilogue: bias + ReLU
    const float4 bv = *reinterpret_cast<const float4*>(&bias[f0 + tx * TN]);
    #pragma unroll
    for (int i = 0; i < TM; ++i) {
        const int l = l0 + ty * TM + i;
        const float4 o = make_float4(fmaxf(acc[i][0] + bv.x, 0.f),
                                     fmaxf(acc[i][1] + bv.y, 0.f),
                                     fmaxf(acc[i][2] + bv.z, 0.f),
                                     fmaxf(acc[i][3] + bv.w, 0.f));
        *reinterpret_cast<float4*>(
            &out[((size_t)b * SEQL + l) * NF + f0 + tx * TN]) = o;
    }
}

// ---------------------------------------------------------------------------
// kernel_launch — graph-capturable: two kernel launches, stream-ordered dep
// via g_Wt. No allocs, no syncs.
// Inputs (metadata order): x, z, U, V, B_w, b, kernel_size(ignored; KSZ=3)
// ---------------------------------------------------------------------------
extern "C" void kernel_launch(void* const* d_in, const int* in_sizes, int n_in,
                              void* d_out, int out_size)
{
    (void)in_sizes; (void)n_in; (void)out_size;
    const float* x    = (const float*)d_in[0];
    const float* z    = (const float*)d_in[1];
    const float* U    = (const float*)d_in[2];
    const float* V    = (const float*)d_in[3];
    const float* Bw   = (const float*)d_in[4];
    const float* bias = (const float*)d_in[5];
    float* out = (float*)d_out;

    dim3 gA(NJ / BN, DIN / BM, NB);    // (12, 2, 64)
    dyn_weight_kernel<<<gA, 256>>>(z, U, V, Bw);

    dim3 gB(NF / BN, SEQL / BM, NB);   // (4, 4, 64)
    conv_kernel<<<gB, 256>>>(x, bias, out);
}

// round 5
// speedup vs baseline: 2.9228x; 2.9228x over previous
#include <cuda_runtime.h>
#include <cstdint>
#include <math.h>

// Problem constants
#define NB   64
#define SEQL 512
#define DIN  256
#define NF   256
#define KSZ  3
#define NJ   768                 // KSZ*NF

// Static device scratch (no allocs allowed)
__device__ float g_sig[NB * DIN];                  // sigmoid(z)
__device__ float g_Vr [DIN * NJ];                  // rna(V)            [e][j]
__device__ float g_xr [NB * SEQL * DIN];           // rna(x)            33.5 MB
__device__ float g_Ub [NB * DIN * DIN];            // rna(U * sig_b)    16.8 MB [b][d][e]
__device__ float g_Wt [NB * KSZ * DIN * NF];       // weights           50.3 MB [b][k][d][f]

// ---------------------------------------------------------------------------
// Helpers
// ---------------------------------------------------------------------------
__device__ __forceinline__ uint32_t smem_u32(const void* p) {
    uint32_t a;
    asm("{ .reg .u64 t; cvta.to.shared.u64 t, %1; cvt.u32.u64 %0, t; }"
        : "=r"(a) : "l"(p));
    return a;
}
__device__ __forceinline__ float rna(float x) {
    uint32_t u;
    asm("cvt.rna.tf32.f32 %0, %1;" : "=r"(u) : "f"(x));
    return __uint_as_float(u);
}
#define CP16(dst, src) \
    asm volatile("cp.async.cg.shared.global [%0], [%1], 16;" :: "r"(dst), "l"(src))
#define CP16Z(dst, src, sz) \
    asm volatile("cp.async.cg.shared.global [%0], [%1], 16, %2;" :: "r"(dst), "l"(src), "r"(sz))
#define CP_COMMIT() asm volatile("cp.async.commit_group;")
#define CP_WAIT1()  asm volatile("cp.async.wait_group 1;" ::: "memory")
#define CP_WAIT0()  asm volatile("cp.async.wait_group 0;" ::: "memory")

// ---------------------------------------------------------------------------
// SMEM tile formats (per stage, 32 KB; two stages = 64 KB dynamic):
//   As: 128 rows (M) x 32 floats (K), 128 B/row, chunk c4 (0..7) of row r
//       stored at r*128 + ((c4 ^ (r&7))<<4)                 [16384 B]
//   Bs:  32 rows (K) x 128 floats (N), 512 B/row, chunk c4 (0..31) of row r
//       stored at r*512 + ((c4 ^ ((2r)&31))<<4)             [16384 B]
// Both fragment-load patterns are bank-conflict-free (verified bank maps).
// ---------------------------------------------------------------------------
#define STAGE_BYTES 32768
#define SMEM_BYTES  65536

// One BK=32 slab of MMAs: warp tile 32(M) x 64(N), m16n8k8 tf32.
__device__ __forceinline__ void tile_mma(float* __restrict__ acc,
                                         const char* __restrict__ As,
                                         const char* __restrict__ Bs,
                                         int gid, int tig, int wm, int wn)
{
    const int nqb = wn * 16 + (gid >> 2);
    const int na  = (gid & 3) * 4;
    const char* Am = As + (wm * 32 + gid) * 128 + tig * 4;

    #pragma unroll
    for (int ks = 0; ks < 4; ++ks) {
        const int ax0 = ((2 * ks)     ^ gid) << 4;
        const int ax1 = ((2 * ks + 1) ^ gid) << 4;
        uint32_t a[2][4];
        #pragma unroll
        for (int mi = 0; mi < 2; ++mi) {
            const char* bm = Am + mi * 2048;          // mi*16 rows * 128B
            a[mi][0] = *(const uint32_t*)(bm + ax0);
            a[mi][1] = *(const uint32_t*)(bm + 1024 + ax0);   // +8 rows
            a[mi][2] = *(const uint32_t*)(bm + ax1);
            a[mi][3] = *(const uint32_t*)(bm + 1024 + ax1);
        }
        const int kk0 = ks * 8 + tig, kk1 = kk0 + 4;
        const int g0 = (2 * kk0) & 31, g1 = (2 * kk1) & 31;
        const char* Br0 = Bs + kk0 * 512 + na;
        const char* Br1 = Bs + kk1 * 512 + na;
        #pragma unroll
        for (int ni = 0; ni < 8; ++ni) {
            const int nq = nqb + 2 * ni;
            const uint32_t b0 = *(const uint32_t*)(Br0 + ((nq ^ g0) << 4));
            const uint32_t b1 = *(const uint32_t*)(Br1 + ((nq ^ g1) << 4));
            #pragma unroll
            for (int mi = 0; mi < 2; ++mi) {
                float* c = &acc[(mi * 8 + ni) * 4];
                asm volatile(
                    "mma.sync.aligned.m16n8k8.row.col.f32.tf32.tf32.f32 "
                    "{%0,%1,%2,%3}, {%4,%5,%6,%7}, {%8,%9}, {%0,%1,%2,%3};"
                    : "+f"(c[0]), "+f"(c[1]), "+f"(c[2]), "+f"(c[3])
                    : "r"(a[mi][0]), "r"(a[mi][1]), "r"(a[mi][2]), "r"(a[mi][3]),
                      "r"(b0), "r"(b1));
            }
        }
    }
}

// ---------------------------------------------------------------------------
// Prep 1: rna(x) -> g_xr, rna(V) -> g_Vr, sigmoid(z) -> g_sig
// ---------------------------------------------------------------------------
__global__ void prep1(const float* __restrict__ x,
                      const float* __restrict__ z,
                      const float* __restrict__ V)
{
    const int tid = blockIdx.x * blockDim.x + threadIdx.x;
    const int nth = gridDim.x * blockDim.x;
    const float4* x4 = (const float4*)x;
    float4* xr4 = (float4*)g_xr;
    for (int i = tid; i < NB * SEQL * DIN / 4; i += nth) {
        float4 v = x4[i];
        v.x = rna(v.x); v.y = rna(v.y); v.z = rna(v.z); v.w = rna(v.w);
        xr4[i] = v;
    }
    const float4* V4 = (const float4*)V;
    float4* Vr4 = (float4*)g_Vr;
    for (int i = tid; i < DIN * NJ / 4; i += nth) {
        float4 v = V4[i];
        v.x = rna(v.x); v.y = rna(v.y); v.z = rna(v.z); v.w = rna(v.w);
        Vr4[i] = v;
    }
    for (int i = tid; i < NB * DIN; i += nth)
        g_sig[i] = 1.f / (1.f + expf(-z[i]));
}

// ---------------------------------------------------------------------------
// Prep 2: g_Ub[b][d][e] = rna(U[d][e] * sig[b][e])
// ---------------------------------------------------------------------------
__global__ void prep2(const float* __restrict__ U)
{
    const int b = blockIdx.x, dblk = blockIdx.y;
    const int t = threadIdx.x;
    const int d  = dblk * 4 + (t >> 6);
    const int e4 = (t & 63) * 4;
    const float4 u = *(const float4*)(U + (size_t)d * DIN + e4);
    const float4 s = *(const float4*)(g_sig + b * DIN + e4);
    float4 o;
    o.x = rna(u.x * s.x); o.y = rna(u.y * s.y);
    o.z = rna(u.z * s.z); o.w = rna(u.w * s.w);
    *(float4*)(g_Ub + ((size_t)(b * DIN + d)) * DIN + e4) = o;
}

// ---------------------------------------------------------------------------
// GEMM1: per b: D[d][j] = sum_e Ub[b][d][e] * Vr[e][j]; W = D + Bw
//   M=d (tiles of 128), N=j (tiles of 128), K=e=256 (8 BK-tiles)
//   store g_Wt[b][k][d][f] (k = jtile/2 fixed per CTA), rna-rounded
// ---------------------------------------------------------------------------
__global__ __launch_bounds__(256)
void gemm_w(const float* __restrict__ Bw)
{
    extern __shared__ char sm[];
    const int b = blockIdx.z, m0 = blockIdx.y * 128, n0 = blockIdx.x * 128;
    const int kq = n0 >> 8, f0 = n0 & 255;
    const int tid = (int)threadIdx.x, wid = tid >> 5, lane = tid & 31;
    const int gid = lane >> 2, tig = lane & 3, wm = wid & 3, wn = wid >> 2;

    const uint32_t sb = smem_u32(sm);
    const float* Asrc = g_Ub + (size_t)b * DIN * DIN + (size_t)m0 * DIN;
    const float* Bsrc = g_Vr + n0;

    float acc[64];
    #pragma unroll
    for (int i = 0; i < 64; ++i) acc[i] = 0.f;

    // stage loader
    auto load = [&](int t) {
        const int e0 = t * 32, st = t & 1;
        const uint32_t ab = sb + st * STAGE_BYTES;
        const uint32_t bb = ab + 16384;
        #pragma unroll
        for (int i = 0; i < 4; ++i) {
            const int c = tid + i * 256;
            const int r = c >> 3, c4 = c & 7;
            CP16(ab + r * 128 + ((c4 ^ (r & 7)) << 4),
                 Asrc + (size_t)r * DIN + e0 + c4 * 4);
        }
        #pragma unroll
        for (int i = 0; i < 4; ++i) {
            const int c = tid + i * 256;
            const int r = c >> 5, c4 = c & 31;
            CP16(bb + r * 512 + ((c4 ^ ((2 * r) & 31)) << 4),
                 Bsrc + (size_t)(e0 + r) * NJ + c4 * 4);
        }
        CP_COMMIT();
    };

    load(0);
    for (int t = 0; t < 8; ++t) {
        if (t < 7) { load(t + 1); CP_WAIT1(); } else CP_WAIT0();
        __syncthreads();
        const int st = t & 1;
        tile_mma(acc, sm + st * STAGE_BYTES, sm + st * STAGE_BYTES + 16384,
                 gid, tig, wm, wn);
        __syncthreads();
    }

    // epilogue: + Bw, rna, store to g_Wt[b][kq][d][f]  (f contiguous)
    #pragma unroll
    for (int mi = 0; mi < 2; ++mi)
        #pragma unroll
        for (int h = 0; h < 2; ++h) {
            const int d = m0 + wm * 32 + mi * 16 + gid + 8 * h;
            float* Wrow = g_Wt + (((size_t)(b * KSZ + kq) * DIN + d) * NF) + f0;
            const float* BwRow = Bw + (size_t)d * NJ + n0;
            #pragma unroll
            for (int ni = 0; ni < 8; ++ni) {
                const int jl = wn * 64 + ni * 8 + 2 * tig;
                const float2 bw = *(const float2*)(BwRow + jl);
                const float* c = &acc[(mi * 8 + ni) * 4 + 2 * h];
                float2 w;
                w.x = rna(c[0] + bw.x);
                w.y = rna(c[1] + bw.y);
                *(float2*)(Wrow + jl) = w;
            }
        }
}

// ---------------------------------------------------------------------------
// Conv: per b: out[l][f] = relu( sum_{kd<768} A[l][kd] * Wt[b][kd][f] + bias[f] )
//   A[l][kd] = g_xr[b] flat at (l-1)*256 + kd, zero outside [0, 512*256)
//   M=l (4 tiles of 128), N=f (2 tiles of 128), K=768 (24 BK-tiles)
// ---------------------------------------------------------------------------
__global__ __launch_bounds__(256)
void conv_mma(const float* __restrict__ bias, float* __restrict__ out)
{
    extern __shared__ char sm[];
    const int b = blockIdx.z, l0 = blockIdx.y * 128, f0 = blockIdx.x * 128;
    const int tid = (int)threadIdx.x, wid = tid >> 5, lane = tid & 31;
    const int gid = lane >> 2, tig = lane & 3, wm = wid & 3, wn = wid >> 2;

    const uint32_t sb = smem_u32(sm);
    const float* xb = g_xr + (size_t)b * SEQL * DIN;
    const float* Wb = g_Wt + (size_t)b * KSZ * DIN * NF + f0;

    float acc[64];
    #pragma unroll
    for (int i = 0; i < 64; ++i) acc[i] = 0.f;

    auto load = [&](int t) {
        const int e0 = t * 32, st = t & 1;
        const uint32_t ab = sb + st * STAGE_BYTES;
        const uint32_t bb = ab + 16384;
        #pragma unroll
        for (int i = 0; i < 4; ++i) {
            const int c = tid + i * 256;
            const int r = c >> 3, c4 = c & 7;
            const int idx = (l0 + r - 1) * DIN + e0 + c4 * 4;   // may be <0 / >= limit
            const unsigned ok = ((unsigned)idx < (unsigned)(SEQL * DIN));
            const float* src = xb + (ok ? idx : 0);
            CP16Z(ab + r * 128 + ((c4 ^ (r & 7)) << 4), src, ok ? 16u : 0u);
        }
        #pragma unroll
        for (int i = 0; i < 4; ++i) {
            const int c = tid + i * 256;
            const int r = c >> 5, c4 = c & 31;
            CP16(bb + r * 512 + ((c4 ^ ((2 * r) & 31)) << 4),
                 Wb + (size_t)(e0 + r) * NF + c4 * 4);
        }
        CP_COMMIT();
    };

    load(0);
    for (int t = 0; t < 24; ++t) {
        if (t < 23) { load(t + 1); CP_WAIT1(); } else CP_WAIT0();
        __syncthreads();
        const int st = t & 1;
        tile_mma(acc, sm + st * STAGE_BYTES, sm + st * STAGE_BYTES + 16384,
                 gid, tig, wm, wn);
        __syncthreads();
    }

    // epilogue: + bias, relu, store (f contiguous)
    #pragma unroll
    for (int mi = 0; mi < 2; ++mi)
        #pragma unroll
        for (int h = 0; h < 2; ++h) {
            const int l = l0 + wm * 32 + mi * 16 + gid + 8 * h;
            float* Orow = out + ((size_t)b * SEQL + l) * NF + f0;
            #pragma unroll
            for (int ni = 0; ni < 8; ++ni) {
                const int fl = wn * 64 + ni * 8 + 2 * tig;
                const float2 bv = *(const float2*)(bias + f0 + fl);
                const float* c = &acc[(mi * 8 + ni) * 4 + 2 * h];
                float2 o;
                o.x = fmaxf(c[0] + bv.x, 0.f);
                o.y = fmaxf(c[1] + bv.y, 0.f);
                *(float2*)(Orow + fl) = o;
            }
        }
}

// ---------------------------------------------------------------------------
// kernel_launch: prep1 -> prep2 -> gemm_w -> conv (stream-ordered, capturable)
// Inputs: x, z, U, V, B_w, b, kernel_size(ignored; KSZ=3)
// ---------------------------------------------------------------------------
extern "C" void kernel_launch(void* const* d_in, const int* in_sizes, int n_in,
                              void* d_out, int out_size)
{
    (void)in_sizes; (void)n_in; (void)out_size;
    const float* x    = (const float*)d_in[0];
    const float* z    = (const float*)d_in[1];
    const float* U    = (const float*)d_in[2];
    const float* V    = (const float*)d_in[3];
    const float* Bw   = (const float*)d_in[4];
    const float* bias = (const float*)d_in[5];
    float* out = (float*)d_out;

    static bool attr_done = false;
    if (!attr_done) {
        cudaFuncSetAttribute(gemm_w,   cudaFuncAttributeMaxDynamicSharedMemorySize, SMEM_BYTES);
        cudaFuncSetAttribute(conv_mma, cudaFuncAttributeMaxDynamicSharedMemorySize, SMEM_BYTES);
        attr_done = true;
    }

    prep1<<<2048, 256>>>(x, z, V);
    prep2<<<dim3(NB, DIN / 4), 256>>>(U);
    gemm_w<<<dim3(NJ / 128, DIN / 128, NB), 256, SMEM_BYTES>>>(Bw);
    conv_mma<<<dim3(NF / 128, SEQL / 128, NB), 256, SMEM_BYTES>>>(bias, out);
}